// round 15
// baseline (speedup 1.0000x reference)
#include <cuda_runtime.h>
#include <math.h>
#include <stdint.h>

#define B_  32
#define S_  512
#define D_  768
#define H_  8
#define DK_ 96
#define C_  3
#define QKW 1536   // fused q|k width

// ---------------- scratch (device globals; no allocs allowed) ----------------
__device__ float g_qk    [(long)B_*S_*QKW];
__device__ float g_wqk   [D_*QKW];
__device__ float g_scores[(long)B_*H_*S_*S_];   // 256 MiB
__device__ float g_adj   [(long)B_*S_*S_];
__device__ float g_den   [B_*S_];
__device__ float g_ax    [B_*S_*D_];
__device__ float g_t1    [B_*S_*D_];
__device__ float g_t2    [B_*S_*D_];
__device__ float g_pool  [B_*D_];
__device__ float g_hid   [B_*D_];

// ---------------- bf16x3 helpers ----------------
__device__ __forceinline__ void bsplit2(float x, float y, uint32_t& h, uint32_t& l) {
    uint32_t bx = __float_as_uint(x), by = __float_as_uint(y);
    h = __byte_perm(bx, by, 0x7632);          // {y_hi16, x_hi16}
    float lx = x - __uint_as_float(bx & 0xFFFF0000u);
    float ly = y - __uint_as_float(by & 0xFFFF0000u);
    asm("cvt.rn.bf16x2.f32 %0, %1, %2;" : "=r"(l) : "f"(ly), "f"(lx));
}
__device__ __forceinline__ void mma_bf16(float* c, const uint32_t* a, const uint32_t* b) {
    asm volatile(
        "mma.sync.aligned.m16n8k16.row.col.f32.bf16.bf16.f32 "
        "{%0,%1,%2,%3}, {%4,%5,%6,%7}, {%8,%9}, {%0,%1,%2,%3};"
        : "+f"(c[0]), "+f"(c[1]), "+f"(c[2]), "+f"(c[3])
        : "r"(a[0]), "r"(a[1]), "r"(a[2]), "r"(a[3]), "r"(b[0]), "r"(b[1]));
}
__device__ __forceinline__ void ldsm4(uint32_t& r0, uint32_t& r1,
                                      uint32_t& r2, uint32_t& r3, uint32_t addr) {
    asm volatile("ldmatrix.sync.aligned.m8n8.x4.shared.b16 {%0,%1,%2,%3}, [%4];"
                 : "=r"(r0), "=r"(r1), "=r"(r2), "=r"(r3) : "r"(addr));
}
__device__ __forceinline__ uint32_t smem_addr32(const void* p) {
    uint32_t a;
    asm("{ .reg .u64 t; cvta.to.shared.u64 t, %1; cvt.u32.u64 %0, t; }"
        : "=r"(a) : "l"(p));
    return a;
}

// ---------------- fast exp ----------------
__device__ __forceinline__ float fast_exp(float x) {
    float y = fmaxf(x * 1.4426950408889634f, -126.0f);
    float t = __fadd_rn(y, 12582912.0f);
    float n = __fsub_rn(t, 12582912.0f);
    float f = __fsub_rn(y, n);
    float p = 0.0013333558f;
    p = fmaf(p, f, 0.0096181291f);
    p = fmaf(p, f, 0.0555041087f);
    p = fmaf(p, f, 0.2402265070f);
    p = fmaf(p, f, 0.6931471806f);
    p = fmaf(p, f, 1.0f);
    int e = (int)n;
    return __int_as_float(__float_as_int(p) + (e << 23));
}

// ---------------- weight concat/transpose: [H,D,DK]x2 -> [D, q|k] (K,N) -----
__global__ void wqk_transpose(const float* __restrict__ wq,
                              const float* __restrict__ wk,
                              float* __restrict__ out)
{
    int idx = blockIdx.x * 256 + threadIdx.x;
    if (idx >= H_ * D_ * DK_) return;
    int h = idx / (D_ * DK_);
    int r = idx % (D_ * DK_);
    int d = r / DK_, j = r % DK_;
    out[(long)d * QKW + h * DK_ + j]       = wq[idx];
    out[(long)d * QKW + D_ + h * DK_ + j]  = wk[idx];
}

// ========= bf16x3 GEMM: 128x64 tile, 4 warps of 32x64, KC=16, ldmatrix ======
// TRANSB: B is [N,K] rows; else [K,N]. Two-level batch z = zb*hdiv + zh.
// 3 CTAs/SM: acc 64/thread -> ~145 regs < 170 cap; smem 36.9KB*3 = 111KB.
#define SRW 12
#define ATSZ (128 * SRW)               // 1536 words per A buffer
#define BTSZ (64 * SRW)                // 768 words per B buffer
#define BBASE (4 * ATSZ)               // 6144
#define MMA_SMEM ((4 * ATSZ + 4 * BTSZ) * 4)   // 36864 B

template<bool TRANSB, bool BIAS, bool RELU, bool DENOM>
__global__ __launch_bounds__(128, 3) void gemm_mma(
    const float* __restrict__ A, const float* __restrict__ Bm, float* __restrict__ C,
    int M, int N, int K, int lda, int ldb,
    long sA, long hA, long sB, long hB, long sC, int hdiv,
    const float* __restrict__ bias, const float* __restrict__ denom, int dstride)
{
    extern __shared__ uint32_t sm[];

    const int tid  = threadIdx.x;
    const int wid  = tid >> 5;          // warp = 32-row group
    const int lane = tid & 31;
    const int t    = lane & 3;
    const int g    = lane >> 2;

    const int z  = blockIdx.z;
    const int zb = z / hdiv;
    const int zh = z - zb * hdiv;
    A  += (long)zb * sA + (long)zh * hA;
    Bm += (long)zb * sB + (long)zh * hB;
    C  += (long)z * sC;

    const int m0 = blockIdx.y * 128;
    const int n0 = blockIdx.x * 64;

    // ldmatrix lane offsets (bytes, within a tile buffer)
    const int r8l = lane & 7;
    const uint32_t aoffA = (uint32_t)(((wid * 32 + ((lane >> 3) & 1) * 8 + r8l) * SRW
                                       + (lane >> 4) * 4) * 4);
    const uint32_t aoffB = (uint32_t)((((lane >> 4) * 8 + r8l) * SRW
                                       + ((lane >> 3) & 1) * 4) * 4);
    const uint32_t smaddr = smem_addr32(sm);

    float acc[2][8][4];
#pragma unroll
    for (int i = 0; i < 2; i++)
#pragma unroll
        for (int j = 0; j < 8; j++)
#pragma unroll
            for (int e = 0; e < 4; e++) acc[i][j][e] = 0.0f;

    float4 pa[4], pb[2];

    auto ldgf = [&](int c) {
        const float* ap = A + (long)(m0 + tid) * lda + c * 16;
#pragma unroll
        for (int i = 0; i < 4; i++) pa[i] = *(const float4*)(ap + i * 4);
        const int brow = tid & 63;
        const int bkh  = (tid >> 6) * 8;
        if (TRANSB) {
            const float* bp = Bm + (long)(n0 + brow) * ldb + c * 16 + bkh;
            pb[0] = *(const float4*)(bp);
            pb[1] = *(const float4*)(bp + 4);
        } else {
            const float* bp = Bm + (long)(c * 16 + bkh) * ldb + n0 + brow;
#pragma unroll
            for (int i = 0; i < 2; i++) {
                pb[i].x = bp[(long)(4 * i + 0) * ldb];
                pb[i].y = bp[(long)(4 * i + 1) * ldb];
                pb[i].z = bp[(long)(4 * i + 2) * ldb];
                pb[i].w = bp[(long)(4 * i + 3) * ldb];
            }
        }
    };
    auto stsf = [&](int s) {
        uint32_t hw[8], lw[8];
#pragma unroll
        for (int i = 0; i < 4; i++) {
            bsplit2(pa[i].x, pa[i].y, hw[2*i],   lw[2*i]);
            bsplit2(pa[i].z, pa[i].w, hw[2*i+1], lw[2*i+1]);
        }
        uint32_t* dah = sm + s * ATSZ + tid * SRW;
        uint32_t* dal = sm + (2 + s) * ATSZ + tid * SRW;
        *(uint4*)(dah)     = make_uint4(hw[0], hw[1], hw[2], hw[3]);
        *(uint4*)(dah + 4) = make_uint4(hw[4], hw[5], hw[6], hw[7]);
        *(uint4*)(dal)     = make_uint4(lw[0], lw[1], lw[2], lw[3]);
        *(uint4*)(dal + 4) = make_uint4(lw[4], lw[5], lw[6], lw[7]);
        // B: 8 floats -> 4 hi + 4 lo words
        bsplit2(pb[0].x, pb[0].y, hw[0], lw[0]);
        bsplit2(pb[0].z, pb[0].w, hw[1], lw[1]);
        bsplit2(pb[1].x, pb[1].y, hw[2], lw[2]);
        bsplit2(pb[1].z, pb[1].w, hw[3], lw[3]);
        const int boff = (tid & 63) * SRW + (tid >> 6) * 4;
        uint32_t* dbh = sm + BBASE + s * BTSZ + boff;
        uint32_t* dbl = sm + BBASE + 2 * BTSZ + s * BTSZ + boff;
        *(uint4*)(dbh) = make_uint4(hw[0], hw[1], hw[2], hw[3]);
        *(uint4*)(dbl) = make_uint4(lw[0], lw[1], lw[2], lw[3]);
    };

    auto compute = [&](int s) {
        const uint32_t aHb = smaddr + (uint32_t)((s)     * ATSZ * 4) + aoffA;
        const uint32_t aLb = smaddr + (uint32_t)((2 + s) * ATSZ * 4) + aoffA;
        const uint32_t bHb = smaddr + (uint32_t)((BBASE + s * BTSZ) * 4) + aoffB;
        const uint32_t bLb = smaddr + (uint32_t)((BBASE + (2 + s) * BTSZ) * 4) + aoffB;
        uint32_t ah[2][4], al[2][4];
#pragma unroll
        for (int mt = 0; mt < 2; mt++) {
            const uint32_t o = mt * (16 * SRW * 4);
            ldsm4(ah[mt][0], ah[mt][1], ah[mt][2], ah[mt][3], aHb + o);
            ldsm4(al[mt][0], al[mt][1], al[mt][2], al[mt][3], aLb + o);
        }
#pragma unroll
        for (int p = 0; p < 4; p++) {
            const uint32_t o = p * (16 * SRW * 4);
            uint32_t bh[4], bl[4];
            ldsm4(bh[0], bh[1], bh[2], bh[3], bHb + o);
            ldsm4(bl[0], bl[1], bl[2], bl[3], bLb + o);
#pragma unroll
            for (int mt = 0; mt < 2; mt++) {
                mma_bf16(acc[mt][2*p],     ah[mt], bh);
                mma_bf16(acc[mt][2*p],     ah[mt], bl);
                mma_bf16(acc[mt][2*p],     al[mt], bh);
                mma_bf16(acc[mt][2*p + 1], ah[mt], bh + 2);
                mma_bf16(acc[mt][2*p + 1], ah[mt], bl + 2);
                mma_bf16(acc[mt][2*p + 1], al[mt], bh + 2);
            }
        }
    };

    const int NC = K >> 4;
    ldgf(0); stsf(0);
    __syncthreads();
    for (int it = 1; it < NC; it++) {
        ldgf(it);
        compute((it - 1) & 1);
        stsf(it & 1);
        __syncthreads();
    }
    compute((NC - 1) & 1);

    // ---- epilogue ----
#pragma unroll
    for (int mt = 0; mt < 2; mt++) {
        const int row0 = m0 + wid * 32 + mt * 16 + g;
        const int row1 = row0 + 8;
        float inv0 = 1.0f, inv1 = 1.0f;
        if (DENOM) {
            inv0 = 1.0f / denom[(long)zb * dstride + row0];
            inv1 = 1.0f / denom[(long)zb * dstride + row1];
        }
#pragma unroll
        for (int nt = 0; nt < 8; nt++) {
            const int col = n0 + nt * 8 + 2 * t;
            float bv0 = 0.0f, bv1 = 0.0f;
            if (BIAS) { bv0 = bias[col]; bv1 = bias[col + 1]; }
            float v0 = acc[mt][nt][0] + bv0;
            float v1 = acc[mt][nt][1] + bv1;
            float v2 = acc[mt][nt][2] + bv0;
            float v3 = acc[mt][nt][3] + bv1;
            if (DENOM) { v0 *= inv0; v1 *= inv0; v2 *= inv1; v3 *= inv1; }
            if (RELU) {
                v0 = fmaxf(v0, 0.0f); v1 = fmaxf(v1, 0.0f);
                v2 = fmaxf(v2, 0.0f); v3 = fmaxf(v3, 0.0f);
            }
            *(float2*)&C[(long)row0 * N + col] = make_float2(v0, v1);
            *(float2*)&C[(long)row1 * N + col] = make_float2(v2, v3);
        }
    }
}

// ======= streaming softmax + head-mean: scores[B,H,S,S] -> adj, denom =======
__global__ __launch_bounds__(512, 1) void softmax_mean_kernel(
    const float* __restrict__ scores, const float* __restrict__ fmask,
    float* __restrict__ adj, float* __restrict__ denom)
{
    const int b   = blockIdx.y;
    const int r0  = blockIdx.x * 32;
    const int wid = threadIdx.x >> 5;
    const int lane = threadIdx.x & 31;
    const float rs = 0.10206207261596577f;   // 1/sqrt(96)

    float fmv[16];
#pragma unroll
    for (int c = 0; c < 4; c++) {
        float4 v = *(const float4*)&fmask[b * S_ + c * 128 + lane * 4];
        fmv[c*4+0] = v.x; fmv[c*4+1] = v.y; fmv[c*4+2] = v.z; fmv[c*4+3] = v.w;
    }

#pragma unroll
    for (int rr = 0; rr < 2; rr++) {
        const int i  = r0 + wid * 2 + rr;
        const float fr = fmask[b * S_ + i];
        float acc[16];
#pragma unroll
        for (int e = 0; e < 16; e++) acc[e] = 0.0f;

        for (int h = 0; h < H_; h++) {
            const float* p = scores + ((long)(b * H_ + h) * S_ + i) * S_;
            float ev[16];
#pragma unroll
            for (int c = 0; c < 4; c++) {
                float4 v = *(const float4*)&p[c * 128 + lane * 4];
                ev[c*4+0] = v.x; ev[c*4+1] = v.y; ev[c*4+2] = v.z; ev[c*4+3] = v.w;
            }
            float mx = -INFINITY;
#pragma unroll
            for (int e = 0; e < 16; e++) {
                float vv = (fr * fmv[e] == 0.0f) ? -1e9f : ev[e] * rs;
                ev[e] = vv;
                mx = fmaxf(mx, vv);
            }
            mx = fmaxf(mx, __shfl_xor_sync(0xffffffffu, mx, 1));
            mx = fmaxf(mx, __shfl_xor_sync(0xffffffffu, mx, 2));
            mx = fmaxf(mx, __shfl_xor_sync(0xffffffffu, mx, 4));
            mx = fmaxf(mx, __shfl_xor_sync(0xffffffffu, mx, 8));
            mx = fmaxf(mx, __shfl_xor_sync(0xffffffffu, mx, 16));
            float s = 0.0f;
#pragma unroll
            for (int e = 0; e < 16; e++) {
                float x = fast_exp(ev[e] - mx);
                ev[e] = x;
                s += x;
            }
            s += __shfl_xor_sync(0xffffffffu, s, 1);
            s += __shfl_xor_sync(0xffffffffu, s, 2);
            s += __shfl_xor_sync(0xffffffffu, s, 4);
            s += __shfl_xor_sync(0xffffffffu, s, 8);
            s += __shfl_xor_sync(0xffffffffu, s, 16);
            const float inv = 1.0f / (8.0f * s);
#pragma unroll
            for (int e = 0; e < 16; e++) acc[e] = fmaf(ev[e], inv, acc[e]);
        }

        float* arow = adj + ((long)b * S_ + i) * S_;
#pragma unroll
        for (int c = 0; c < 4; c++) {
            float4 o;
#pragma unroll
            for (int e = 0; e < 4; e++) {
                int j = c * 128 + lane * 4 + e;
                float v = acc[c * 4 + e];
                if (j == i) { denom[b * S_ + i] = 3.0f - v; v = 1.0f; }
                ((float*)&o)[e] = v;
            }
            *(float4*)&arow[c * 128 + lane * 4] = o;
        }
    }
}

// ---------------- small guarded SGEMM (FFN1 only: M=32) ----------------------
template<bool TRANSB, bool BIAS, bool RELU>
__global__ __launch_bounds__(256) void sgemm_small(
    const float* __restrict__ A, const float* __restrict__ Bm, float* __restrict__ C,
    int M, int N, int K, const float* __restrict__ bias)
{
    __shared__ float As[16][68];
    __shared__ float Bs[16][68];
    const int m0 = blockIdx.y * 64, n0 = blockIdx.x * 64;
    const int tid = threadIdx.x;
    const int tx = tid & 15, ty = tid >> 4;
    float acc[4][4];
#pragma unroll
    for (int i = 0; i < 4; i++)
#pragma unroll
        for (int j = 0; j < 4; j++) acc[i][j] = 0.0f;
    const int arow = tid >> 2, akq = (tid & 3) * 4;
    for (int k0 = 0; k0 < K; k0 += 16) {
        float4 av = make_float4(0.f,0.f,0.f,0.f);
        if (m0 + arow < M)
            av = *(const float4*)&A[(long)(m0 + arow) * K + k0 + akq];
        As[akq+0][arow]=av.x; As[akq+1][arow]=av.y;
        As[akq+2][arow]=av.z; As[akq+3][arow]=av.w;
        if (!TRANSB) {
            const int kr = tid >> 4, nq = (tid & 15) * 4;
            float4 bv = make_float4(0.f,0.f,0.f,0.f);
            if (n0 + nq < N)
                bv = *(const float4*)&Bm[(long)(k0+kr)*N + n0 + nq];
            Bs[kr][nq+0]=bv.x; Bs[kr][nq+1]=bv.y; Bs[kr][nq+2]=bv.z; Bs[kr][nq+3]=bv.w;
        } else {
            const int nrow = tid >> 2, kq = (tid & 3) * 4;
            float4 bv = make_float4(0.f,0.f,0.f,0.f);
            if (n0 + nrow < N)
                bv = *(const float4*)&Bm[(long)(n0+nrow)*K + k0 + kq];
            Bs[kq+0][nrow]=bv.x; Bs[kq+1][nrow]=bv.y; Bs[kq+2][nrow]=bv.z; Bs[kq+3][nrow]=bv.w;
        }
        __syncthreads();
#pragma unroll
        for (int kk = 0; kk < 16; kk++) {
            float4 a = *(const float4*)&As[kk][ty*4];
            float4 b = *(const float4*)&Bs[kk][tx*4];
            acc[0][0]=fmaf(a.x,b.x,acc[0][0]); acc[0][1]=fmaf(a.x,b.y,acc[0][1]);
            acc[0][2]=fmaf(a.x,b.z,acc[0][2]); acc[0][3]=fmaf(a.x,b.w,acc[0][3]);
            acc[1][0]=fmaf(a.y,b.x,acc[1][0]); acc[1][1]=fmaf(a.y,b.y,acc[1][1]);
            acc[1][2]=fmaf(a.y,b.z,acc[1][2]); acc[1][3]=fmaf(a.y,b.w,acc[1][3]);
            acc[2][0]=fmaf(a.z,b.x,acc[2][0]); acc[2][1]=fmaf(a.z,b.y,acc[2][1]);
            acc[2][2]=fmaf(a.z,b.z,acc[2][2]); acc[2][3]=fmaf(a.z,b.w,acc[2][3]);
            acc[3][0]=fmaf(a.w,b.x,acc[3][0]); acc[3][1]=fmaf(a.w,b.y,acc[3][1]);
            acc[3][2]=fmaf(a.w,b.z,acc[3][2]); acc[3][3]=fmaf(a.w,b.w,acc[3][3]);
        }
        __syncthreads();
    }
#pragma unroll
    for (int i = 0; i < 4; i++) {
        int m = m0 + ty*4 + i;
        if (m >= M) continue;
#pragma unroll
        for (int j = 0; j < 4; j++) {
            int n = n0 + tx*4 + j;
            if (n < N) {
                float v = acc[i][j];
                if (BIAS) v += bias[n];
                if (RELU) v = fmaxf(v, 0.0f);
                C[(long)m * N + n] = v;
            }
        }
    }
}

// ---------------- aspect max-pool ----------------
__global__ void pool_kernel(const float* __restrict__ tok,
                            const int* __restrict__ am,
                            float* __restrict__ pool)
{
    int d = blockIdx.x * 256 + threadIdx.x;
    int b = blockIdx.y;
    if (d >= D_) return;
    const float* tp = tok + (long)b * S_ * D_;
    const int*   ap = am + b * S_;
    float m = -10000.0f;
#pragma unroll 8
    for (int s = 0; s < S_; s++) {
        float v = (ap[s] == 1) ? tp[(long)s * D_ + d] : -10000.0f;
        m = fmaxf(m, v);
    }
    pool[b * D_ + d] = m;
}

// ---------------- FFN2 + output assembly ----------------
__global__ void ffn2_kernel(const float* __restrict__ h,
                            const float* __restrict__ w2,
                            const float* __restrict__ b2,
                            const float* __restrict__ pool,
                            float* __restrict__ out)
{
    int bid = blockIdx.x;
    if (bid < 96) {
        int idx = bid * 256 + threadIdx.x;
        out[B_ * C_ + idx] = pool[idx];
    } else {
        int t = threadIdx.x;
        if (t < B_ * C_) {
            int b = t / C_, c = t % C_;
            const float* hp = h + b * D_;
            const float* wp = w2 + c * D_;
            float s = b2[c];
            for (int d = 0; d < D_; d++) s = fmaf(hp[d], wp[d], s);
            out[b * C_ + c] = s;
        }
    }
}

// ---------------- orchestration ----------------
extern "C" void kernel_launch(void* const* d_in, const int* in_sizes, int n_in,
                              void* d_out, int out_size)
{
    const float* x     = (const float*)d_in[0];
    const float* fmask = (const float*)d_in[1];
    const int*   amask = (const int*)  d_in[2];
    const float* wq    = (const float*)d_in[3];
    const float* wk    = (const float*)d_in[4];
    const float* gw    = (const float*)d_in[5];
    const float* gb    = (const float*)d_in[6];
    const float* w1    = (const float*)d_in[7];
    const float* b1    = (const float*)d_in[8];
    const float* w2    = (const float*)d_in[9];
    const float* b2    = (const float*)d_in[10];
    float* out = (float*)d_out;

    float *pqk, *pwqk, *pscores, *padj, *pden, *pax, *pt1, *pt2, *ppool, *phid;
    cudaGetSymbolAddress((void**)&pqk,    g_qk);
    cudaGetSymbolAddress((void**)&pwqk,   g_wqk);
    cudaGetSymbolAddress((void**)&pscores,g_scores);
    cudaGetSymbolAddress((void**)&padj,   g_adj);
    cudaGetSymbolAddress((void**)&pden,   g_den);
    cudaGetSymbolAddress((void**)&pax,    g_ax);
    cudaGetSymbolAddress((void**)&pt1,    g_t1);
    cudaGetSymbolAddress((void**)&pt2,    g_t2);
    cudaGetSymbolAddress((void**)&ppool,  g_pool);
    cudaGetSymbolAddress((void**)&phid,   g_hid);

    cudaFuncSetAttribute(gemm_mma<false,false,false,false>,
                         cudaFuncAttributeMaxDynamicSharedMemorySize, MMA_SMEM);
    cudaFuncSetAttribute(gemm_mma<true,false,false,false>,
                         cudaFuncAttributeMaxDynamicSharedMemorySize, MMA_SMEM);
    cudaFuncSetAttribute(gemm_mma<true,true,true,true>,
                         cudaFuncAttributeMaxDynamicSharedMemorySize, MMA_SMEM);

    // 0) concat/transpose weights -> [768][1536] (K,N)
    wqk_transpose<<<(H_*D_*DK_ + 255) / 256, 256>>>(wq, wk, pwqk);

    // 1) fused Q|K projection: [16384 x 768] @ [768 x 1536]
    gemm_mma<false,false,false,false><<<dim3(QKW/64, (B_*S_)/128, 1), 128, MMA_SMEM>>>(
        x, pwqk, pqk, B_*S_, QKW, D_, D_, QKW,
        0L, 0L, 0L, 0L, 0L, 1, nullptr, nullptr, 0);

    // 2a) scores[b,h] = Q_bh @ K_bh^T  (batched over z = b*8+h, K=96)
    gemm_mma<true,false,false,false><<<dim3(8, 4, B_*H_), 128, MMA_SMEM>>>(
        pqk, pqk + D_, pscores, S_, S_, DK_, QKW, QKW,
        (long)S_*QKW, (long)DK_, (long)S_*QKW, (long)DK_, (long)S_*S_, H_,
        nullptr, nullptr, 0);

    // 2b) streaming softmax + head-mean -> adj, denom
    softmax_mean_kernel<<<dim3(16, B_), 512>>>(pscores, fmask, padj, pden);

    // 3) GCN layers
    {
        dim3 g(D_/64, S_/128, B_);   // (12, 4, 32)
        gemm_mma<false,false,false,false><<<g, 128, MMA_SMEM>>>(
            padj, x, pax, S_, D_, S_, S_, D_,
            (long)S_*S_, 0L, (long)S_*D_, 0L, (long)S_*D_, 1, nullptr, nullptr, 0);
        gemm_mma<true,true,true,true><<<g, 128, MMA_SMEM>>>(
            pax, gw, pt1, S_, D_, D_, D_, D_,
            (long)S_*D_, 0L, 0L, 0L, (long)S_*D_, 1, gb, pden, S_);
        gemm_mma<false,false,false,false><<<g, 128, MMA_SMEM>>>(
            padj, pt1, pax, S_, D_, S_, S_, D_,
            (long)S_*S_, 0L, (long)S_*D_, 0L, (long)S_*D_, 1, nullptr, nullptr, 0);
        gemm_mma<true,true,true,true><<<g, 128, MMA_SMEM>>>(
            pax, gw + (long)D_*D_, pt2, S_, D_, D_, D_, D_,
            (long)S_*D_, 0L, 0L, 0L, (long)S_*D_, 1, gb + D_, pden, S_);
    }

    // 4) aspect max-pool -> preds
    pool_kernel<<<dim3(3, B_), 256>>>(pt2, amask, ppool);

    // 5) FFN1
    sgemm_small<true,true,true><<<dim3(12, 1, 1), 256>>>(
        ppool, w1, phid, B_, D_, D_, b1);

    // 6) FFN2 + output
    ffn2_kernel<<<97, 256>>>(phid, w2, b2, ppool, out);
}

// round 16
// speedup vs baseline: 1.2590x; 1.2590x over previous
#include <cuda_runtime.h>
#include <math.h>
#include <stdint.h>

#define B_  32
#define S_  512
#define D_  768
#define H_  8
#define DK_ 96
#define C_  3
#define QKW 1536   // fused q|k width

// ---------------- scratch (device globals; no allocs allowed) ----------------
__device__ float    g_qk    [(long)B_*S_*QKW];
__device__ float    g_wqk   [D_*QKW];
__device__ float    g_scores[(long)B_*H_*S_*S_];   // 256 MiB
__device__ float    g_adj   [(long)B_*S_*S_];
__device__ float    g_den   [B_*S_];
__device__ float    g_ax    [B_*S_*D_];
__device__ float    g_t1    [B_*S_*D_];
__device__ unsigned g_poolu [B_*D_];
__device__ float    g_pool  [B_*D_];
__device__ float    g_hid   [B_*D_];

// ---------------- bf16x3 helpers ----------------
__device__ __forceinline__ void bsplit2(float x, float y, uint32_t& h, uint32_t& l) {
    uint32_t bx = __float_as_uint(x), by = __float_as_uint(y);
    h = __byte_perm(bx, by, 0x7632);          // {y_hi16, x_hi16}
    float lx = x - __uint_as_float(bx & 0xFFFF0000u);
    float ly = y - __uint_as_float(by & 0xFFFF0000u);
    asm("cvt.rn.bf16x2.f32 %0, %1, %2;" : "=r"(l) : "f"(ly), "f"(lx));
}
__device__ __forceinline__ void mma_bf16(float* c, const uint32_t* a, const uint32_t* b) {
    asm volatile(
        "mma.sync.aligned.m16n8k16.row.col.f32.bf16.bf16.f32 "
        "{%0,%1,%2,%3}, {%4,%5,%6,%7}, {%8,%9}, {%0,%1,%2,%3};"
        : "+f"(c[0]), "+f"(c[1]), "+f"(c[2]), "+f"(c[3])
        : "r"(a[0]), "r"(a[1]), "r"(a[2]), "r"(a[3]), "r"(b[0]), "r"(b[1]));
}
__device__ __forceinline__ void ldsm4(uint32_t& r0, uint32_t& r1,
                                      uint32_t& r2, uint32_t& r3, uint32_t addr) {
    asm volatile("ldmatrix.sync.aligned.m8n8.x4.shared.b16 {%0,%1,%2,%3}, [%4];"
                 : "=r"(r0), "=r"(r1), "=r"(r2), "=r"(r3) : "r"(addr));
}
__device__ __forceinline__ uint32_t smem_addr32(const void* p) {
    uint32_t a;
    asm("{ .reg .u64 t; cvta.to.shared.u64 t, %1; cvt.u32.u64 %0, t; }"
        : "=r"(a) : "l"(p));
    return a;
}
// order-preserving float->uint key (monotonic)
__device__ __forceinline__ unsigned fkey(float f) {
    int i = __float_as_int(f);
    return (i >= 0) ? ((unsigned)i | 0x80000000u) : ~(unsigned)i;
}
__device__ __forceinline__ float funkey(unsigned u) {
    int i = (u & 0x80000000u) ? (int)(u & 0x7FFFFFFFu) : (int)(~u);
    return __int_as_float(i);
}

// ---------------- fast exp ----------------
__device__ __forceinline__ float fast_exp(float x) {
    float y = fmaxf(x * 1.4426950408889634f, -126.0f);
    float t = __fadd_rn(y, 12582912.0f);
    float n = __fsub_rn(t, 12582912.0f);
    float f = __fsub_rn(y, n);
    float p = 0.0013333558f;
    p = fmaf(p, f, 0.0096181291f);
    p = fmaf(p, f, 0.0555041087f);
    p = fmaf(p, f, 0.2402265070f);
    p = fmaf(p, f, 0.6931471806f);
    p = fmaf(p, f, 1.0f);
    int e = (int)n;
    return __int_as_float(__float_as_int(p) + (e << 23));
}

// ---------------- weight concat/transpose: [H,D,DK]x2 -> [D, q|k] (K,N) -----
__global__ void wqk_transpose(const float* __restrict__ wq,
                              const float* __restrict__ wk,
                              float* __restrict__ out,
                              unsigned* __restrict__ poolu)
{
    int idx = blockIdx.x * 256 + threadIdx.x;
    if (idx < B_ * D_) poolu[idx] = 0x39E3BFFFu;   // fkey(-10000.0f)
    if (idx >= H_ * D_ * DK_) return;
    int h = idx / (D_ * DK_);
    int r = idx % (D_ * DK_);
    int d = r / DK_, j = r % DK_;
    out[(long)d * QKW + h * DK_ + j]       = wq[idx];
    out[(long)d * QKW + D_ + h * DK_ + j]  = wk[idx];
}

// ========= bf16x3 GEMM: 128x128 tile, 4 warps of 64x64, KC=16, ldmatrix =====
// TRANSB: B is [N,K] rows; else [K,N]. Two-level batch z = zb*hdiv + zh.
// POOL: skip C store; aspect-masked column-max reduced into poolu via atomicMax.
#define SRW 12
#define TSZ (128 * SRW)
#define MMA_SMEM (8 * TSZ * 4)          // 49152 B

template<bool TRANSB, bool BIAS, bool RELU, bool DENOM, bool POOL>
__global__ __launch_bounds__(128, 2) void gemm_mma(
    const float* __restrict__ A, const float* __restrict__ Bm, float* __restrict__ C,
    int M, int N, int K, int lda, int ldb,
    long sA, long hA, long sB, long hB, long sC, int hdiv,
    const float* __restrict__ bias, const float* __restrict__ denom, int dstride,
    const int* __restrict__ am, unsigned* __restrict__ poolu)
{
    extern __shared__ uint32_t sm[];

    const int tid  = threadIdx.x;
    const int wid  = tid >> 5;
    const int lane = tid & 31;
    const int t    = lane & 3;
    const int g    = lane >> 2;
    const int wr   = wid & 1;
    const int wc   = wid >> 1;

    const int z  = blockIdx.z;
    const int zb = z / hdiv;
    const int zh = z - zb * hdiv;
    A  += (long)zb * sA + (long)zh * hA;
    Bm += (long)zb * sB + (long)zh * hB;
    C  += (long)z * sC;

    const int m0 = blockIdx.y * 128;
    const int n0 = blockIdx.x * 128;

    // ldmatrix lane offsets (bytes, within a tile buffer)
    const int r8l = lane & 7;
    const uint32_t aoffA = (uint32_t)(((wr * 64 + ((lane >> 3) & 1) * 8 + r8l) * SRW
                                       + (lane >> 4) * 4) * 4);
    const uint32_t aoffB = (uint32_t)(((wc * 64 + (lane >> 4) * 8 + r8l) * SRW
                                       + ((lane >> 3) & 1) * 4) * 4);
    const uint32_t smaddr = smem_addr32(sm);

    float acc[4][8][4];
#pragma unroll
    for (int i = 0; i < 4; i++)
#pragma unroll
        for (int j = 0; j < 8; j++)
#pragma unroll
            for (int e = 0; e < 4; e++) acc[i][j][e] = 0.0f;

    float4 pa[4], pb[4];

    auto ldgf = [&](int c) {
        const float* ap = A + (long)(m0 + tid) * lda + c * 16;
#pragma unroll
        for (int i = 0; i < 4; i++) pa[i] = *(const float4*)(ap + i * 4);
        if (TRANSB) {
            const float* bp = Bm + (long)(n0 + tid) * ldb + c * 16;
#pragma unroll
            for (int i = 0; i < 4; i++) pb[i] = *(const float4*)(bp + i * 4);
        } else {
            const float* bp = Bm + (long)(c * 16) * ldb + n0 + tid;
#pragma unroll
            for (int i = 0; i < 4; i++) {
                pb[i].x = bp[(long)(4 * i + 0) * ldb];
                pb[i].y = bp[(long)(4 * i + 1) * ldb];
                pb[i].z = bp[(long)(4 * i + 2) * ldb];
                pb[i].w = bp[(long)(4 * i + 3) * ldb];
            }
        }
    };
    auto stsf = [&](int s) {
        uint32_t hw[8], lw[8];
#pragma unroll
        for (int i = 0; i < 4; i++) {
            bsplit2(pa[i].x, pa[i].y, hw[2*i],   lw[2*i]);
            bsplit2(pa[i].z, pa[i].w, hw[2*i+1], lw[2*i+1]);
        }
        uint32_t* dah = sm + s * TSZ + tid * SRW;
        uint32_t* dal = sm + (2 + s) * TSZ + tid * SRW;
        *(uint4*)(dah)     = make_uint4(hw[0], hw[1], hw[2], hw[3]);
        *(uint4*)(dah + 4) = make_uint4(hw[4], hw[5], hw[6], hw[7]);
        *(uint4*)(dal)     = make_uint4(lw[0], lw[1], lw[2], lw[3]);
        *(uint4*)(dal + 4) = make_uint4(lw[4], lw[5], lw[6], lw[7]);
#pragma unroll
        for (int i = 0; i < 4; i++) {
            bsplit2(pb[i].x, pb[i].y, hw[2*i],   lw[2*i]);
            bsplit2(pb[i].z, pb[i].w, hw[2*i+1], lw[2*i+1]);
        }
        uint32_t* dbh = sm + (4 + s) * TSZ + tid * SRW;
        uint32_t* dbl = sm + (6 + s) * TSZ + tid * SRW;
        *(uint4*)(dbh)     = make_uint4(hw[0], hw[1], hw[2], hw[3]);
        *(uint4*)(dbh + 4) = make_uint4(hw[4], hw[5], hw[6], hw[7]);
        *(uint4*)(dbl)     = make_uint4(lw[0], lw[1], lw[2], lw[3]);
        *(uint4*)(dbl + 4) = make_uint4(lw[4], lw[5], lw[6], lw[7]);
    };

    auto compute = [&](int s) {
        const uint32_t aHb = smaddr + (uint32_t)((s)     * TSZ * 4) + aoffA;
        const uint32_t aLb = smaddr + (uint32_t)((2 + s) * TSZ * 4) + aoffA;
        const uint32_t bHb = smaddr + (uint32_t)((4 + s) * TSZ * 4) + aoffB;
        const uint32_t bLb = smaddr + (uint32_t)((6 + s) * TSZ * 4) + aoffB;
        uint32_t ah[4][4], al[4][4];
#pragma unroll
        for (int mt = 0; mt < 4; mt++) {
            const uint32_t o = mt * (16 * SRW * 4);
            ldsm4(ah[mt][0], ah[mt][1], ah[mt][2], ah[mt][3], aHb + o);
            ldsm4(al[mt][0], al[mt][1], al[mt][2], al[mt][3], aLb + o);
        }
#pragma unroll
        for (int p = 0; p < 4; p++) {
            const uint32_t o = p * (16 * SRW * 4);
            uint32_t bh[4], bl[4];
            ldsm4(bh[0], bh[1], bh[2], bh[3], bHb + o);
            ldsm4(bl[0], bl[1], bl[2], bl[3], bLb + o);
#pragma unroll
            for (int mt = 0; mt < 4; mt++) {
                mma_bf16(acc[mt][2*p],     ah[mt], bh);
                mma_bf16(acc[mt][2*p],     ah[mt], bl);
                mma_bf16(acc[mt][2*p],     al[mt], bh);
                mma_bf16(acc[mt][2*p + 1], ah[mt], bh + 2);
                mma_bf16(acc[mt][2*p + 1], ah[mt], bl + 2);
                mma_bf16(acc[mt][2*p + 1], al[mt], bh + 2);
            }
        }
    };

    const int NC = K >> 4;
    ldgf(0); stsf(0);
    __syncthreads();
    for (int it = 1; it < NC; it++) {
        ldgf(it);
        compute((it - 1) & 1);
        stsf(it & 1);
        __syncthreads();
    }
    compute((NC - 1) & 1);

    // ---- epilogue ----
    float cmax[8][2];
    if (POOL) {
#pragma unroll
        for (int nt = 0; nt < 8; nt++) { cmax[nt][0] = -1e30f; cmax[nt][1] = -1e30f; }
    }
#pragma unroll
    for (int mt = 0; mt < 4; mt++) {
        const int row0 = m0 + wr * 64 + mt * 16 + g;
        const int row1 = row0 + 8;
        float inv0 = 1.0f, inv1 = 1.0f;
        if (DENOM) {
            inv0 = 1.0f / denom[(long)zb * dstride + row0];
            inv1 = 1.0f / denom[(long)zb * dstride + row1];
        }
        float mk0 = 0.0f, mk1 = 0.0f;
        if (POOL) {
            mk0 = (am[(long)zb * S_ + row0] == 1) ? 1.0f : 0.0f;
            mk1 = (am[(long)zb * S_ + row1] == 1) ? 1.0f : 0.0f;
        }
#pragma unroll
        for (int nt = 0; nt < 8; nt++) {
            const int col = n0 + wc * 64 + nt * 8 + 2 * t;
            float bv0 = 0.0f, bv1 = 0.0f;
            if (BIAS) { bv0 = bias[col]; bv1 = bias[col + 1]; }
            float v0 = acc[mt][nt][0] + bv0;
            float v1 = acc[mt][nt][1] + bv1;
            float v2 = acc[mt][nt][2] + bv0;
            float v3 = acc[mt][nt][3] + bv1;
            if (DENOM) { v0 *= inv0; v1 *= inv0; v2 *= inv1; v3 *= inv1; }
            if (RELU) {
                v0 = fmaxf(v0, 0.0f); v1 = fmaxf(v1, 0.0f);
                v2 = fmaxf(v2, 0.0f); v3 = fmaxf(v3, 0.0f);
            }
            if (POOL) {
                cmax[nt][0] = fmaxf(cmax[nt][0], mk0 ? v0 : -1e30f);
                cmax[nt][0] = fmaxf(cmax[nt][0], mk1 ? v2 : -1e30f);
                cmax[nt][1] = fmaxf(cmax[nt][1], mk0 ? v1 : -1e30f);
                cmax[nt][1] = fmaxf(cmax[nt][1], mk1 ? v3 : -1e30f);
            } else {
                *(float2*)&C[(long)row0 * N + col] = make_float2(v0, v1);
                *(float2*)&C[(long)row1 * N + col] = make_float2(v2, v3);
            }
        }
    }
    if (POOL) {
        // cross-thread reduce: part[col_local(128)][slot(16)], stride 17
        __syncthreads();
        float* part = (float*)sm;
        const int slot = wr * 8 + g;
#pragma unroll
        for (int nt = 0; nt < 8; nt++) {
            const int c0 = wc * 64 + nt * 8 + 2 * t;
            part[(c0    ) * 17 + slot] = cmax[nt][0];
            part[(c0 + 1) * 17 + slot] = cmax[nt][1];
        }
        __syncthreads();
        if (tid < 128) {
            float m = -1e30f;
#pragma unroll
            for (int j = 0; j < 16; j++) m = fmaxf(m, part[tid * 17 + j]);
            atomicMax(&poolu[(long)zb * D_ + n0 + tid], fkey(m));
        }
    }
}

// ---------------- pool decode: uint keys -> float ----------------
__global__ void pool_decode(const unsigned* __restrict__ pu, float* __restrict__ pf)
{
    int i = blockIdx.x * 256 + threadIdx.x;
    if (i < B_ * D_) pf[i] = funkey(pu[i]);
}

// ======= streaming softmax + head-mean: scores[B,H,S,S] -> adj, denom =======
__global__ __launch_bounds__(512, 1) void softmax_mean_kernel(
    const float* __restrict__ scores, const float* __restrict__ fmask,
    float* __restrict__ adj, float* __restrict__ denom)
{
    const int b   = blockIdx.y;
    const int r0  = blockIdx.x * 32;
    const int wid = threadIdx.x >> 5;
    const int lane = threadIdx.x & 31;
    const float rs = 0.10206207261596577f;   // 1/sqrt(96)

    float fmv[16];
#pragma unroll
    for (int c = 0; c < 4; c++) {
        float4 v = *(const float4*)&fmask[b * S_ + c * 128 + lane * 4];
        fmv[c*4+0] = v.x; fmv[c*4+1] = v.y; fmv[c*4+2] = v.z; fmv[c*4+3] = v.w;
    }

#pragma unroll
    for (int rr = 0; rr < 2; rr++) {
        const int i  = r0 + wid * 2 + rr;
        const float fr = fmask[b * S_ + i];
        float acc[16];
#pragma unroll
        for (int e = 0; e < 16; e++) acc[e] = 0.0f;

        for (int h = 0; h < H_; h++) {
            const float* p = scores + ((long)(b * H_ + h) * S_ + i) * S_;
            float ev[16];
#pragma unroll
            for (int c = 0; c < 4; c++) {
                float4 v = *(const float4*)&p[c * 128 + lane * 4];
                ev[c*4+0] = v.x; ev[c*4+1] = v.y; ev[c*4+2] = v.z; ev[c*4+3] = v.w;
            }
            float mx = -INFINITY;
#pragma unroll
            for (int e = 0; e < 16; e++) {
                float vv = (fr * fmv[e] == 0.0f) ? -1e9f : ev[e] * rs;
                ev[e] = vv;
                mx = fmaxf(mx, vv);
            }
            mx = fmaxf(mx, __shfl_xor_sync(0xffffffffu, mx, 1));
            mx = fmaxf(mx, __shfl_xor_sync(0xffffffffu, mx, 2));
            mx = fmaxf(mx, __shfl_xor_sync(0xffffffffu, mx, 4));
            mx = fmaxf(mx, __shfl_xor_sync(0xffffffffu, mx, 8));
            mx = fmaxf(mx, __shfl_xor_sync(0xffffffffu, mx, 16));
            float s = 0.0f;
#pragma unroll
            for (int e = 0; e < 16; e++) {
                float x = fast_exp(ev[e] - mx);
                ev[e] = x;
                s += x;
            }
            s += __shfl_xor_sync(0xffffffffu, s, 1);
            s += __shfl_xor_sync(0xffffffffu, s, 2);
            s += __shfl_xor_sync(0xffffffffu, s, 4);
            s += __shfl_xor_sync(0xffffffffu, s, 8);
            s += __shfl_xor_sync(0xffffffffu, s, 16);
            const float inv = 1.0f / (8.0f * s);
#pragma unroll
            for (int e = 0; e < 16; e++) acc[e] = fmaf(ev[e], inv, acc[e]);
        }

        float* arow = adj + ((long)b * S_ + i) * S_;
#pragma unroll
        for (int c = 0; c < 4; c++) {
            float4 o;
#pragma unroll
            for (int e = 0; e < 4; e++) {
                int j = c * 128 + lane * 4 + e;
                float v = acc[c * 4 + e];
                if (j == i) { denom[b * S_ + i] = 3.0f - v; v = 1.0f; }
                ((float*)&o)[e] = v;
            }
            *(float4*)&arow[c * 128 + lane * 4] = o;
        }
    }
}

// ---------------- small guarded SGEMM (FFN1 only: M=32) ----------------------
template<bool TRANSB, bool BIAS, bool RELU>
__global__ __launch_bounds__(256) void sgemm_small(
    const float* __restrict__ A, const float* __restrict__ Bm, float* __restrict__ C,
    int M, int N, int K, const float* __restrict__ bias)
{
    __shared__ float As[16][68];
    __shared__ float Bs[16][68];
    const int m0 = blockIdx.y * 64, n0 = blockIdx.x * 64;
    const int tid = threadIdx.x;
    const int tx = tid & 15, ty = tid >> 4;
    float acc[4][4];
#pragma unroll
    for (int i = 0; i < 4; i++)
#pragma unroll
        for (int j = 0; j < 4; j++) acc[i][j] = 0.0f;
    const int arow = tid >> 2, akq = (tid & 3) * 4;
    for (int k0 = 0; k0 < K; k0 += 16) {
        float4 av = make_float4(0.f,0.f,0.f,0.f);
        if (m0 + arow < M)
            av = *(const float4*)&A[(long)(m0 + arow) * K + k0 + akq];
        As[akq+0][arow]=av.x; As[akq+1][arow]=av.y;
        As[akq+2][arow]=av.z; As[akq+3][arow]=av.w;
        if (!TRANSB) {
            const int kr = tid >> 4, nq = (tid & 15) * 4;
            float4 bv = make_float4(0.f,0.f,0.f,0.f);
            if (n0 + nq < N)
                bv = *(const float4*)&Bm[(long)(k0+kr)*N + n0 + nq];
            Bs[kr][nq+0]=bv.x; Bs[kr][nq+1]=bv.y; Bs[kr][nq+2]=bv.z; Bs[kr][nq+3]=bv.w;
        } else {
            const int nrow = tid >> 2, kq = (tid & 3) * 4;
            float4 bv = make_float4(0.f,0.f,0.f,0.f);
            if (n0 + nrow < N)
                bv = *(const float4*)&Bm[(long)(n0+nrow)*K + k0 + kq];
            Bs[kq+0][nrow]=bv.x; Bs[kq+1][nrow]=bv.y; Bs[kq+2][nrow]=bv.z; Bs[kq+3][nrow]=bv.w;
        }
        __syncthreads();
#pragma unroll
        for (int kk = 0; kk < 16; kk++) {
            float4 a = *(const float4*)&As[kk][ty*4];
            float4 b = *(const float4*)&Bs[kk][tx*4];
            acc[0][0]=fmaf(a.x,b.x,acc[0][0]); acc[0][1]=fmaf(a.x,b.y,acc[0][1]);
            acc[0][2]=fmaf(a.x,b.z,acc[0][2]); acc[0][3]=fmaf(a.x,b.w,acc[0][3]);
            acc[1][0]=fmaf(a.y,b.x,acc[1][0]); acc[1][1]=fmaf(a.y,b.y,acc[1][1]);
            acc[1][2]=fmaf(a.y,b.z,acc[1][2]); acc[1][3]=fmaf(a.y,b.w,acc[1][3]);
            acc[2][0]=fmaf(a.z,b.x,acc[2][0]); acc[2][1]=fmaf(a.z,b.y,acc[2][1]);
            acc[2][2]=fmaf(a.z,b.z,acc[2][2]); acc[2][3]=fmaf(a.z,b.w,acc[2][3]);
            acc[3][0]=fmaf(a.w,b.x,acc[3][0]); acc[3][1]=fmaf(a.w,b.y,acc[3][1]);
            acc[3][2]=fmaf(a.w,b.z,acc[3][2]); acc[3][3]=fmaf(a.w,b.w,acc[3][3]);
        }
        __syncthreads();
    }
#pragma unroll
    for (int i = 0; i < 4; i++) {
        int m = m0 + ty*4 + i;
        if (m >= M) continue;
#pragma unroll
        for (int j = 0; j < 4; j++) {
            int n = n0 + tx*4 + j;
            if (n < N) {
                float v = acc[i][j];
                if (BIAS) v += bias[n];
                if (RELU) v = fmaxf(v, 0.0f);
                C[(long)m * N + n] = v;
            }
        }
    }
}

// ---------------- FFN2 + output assembly ----------------
__global__ void ffn2_kernel(const float* __restrict__ h,
                            const float* __restrict__ w2,
                            const float* __restrict__ b2,
                            const float* __restrict__ pool,
                            float* __restrict__ out)
{
    int bid = blockIdx.x;
    if (bid < 96) {
        int idx = bid * 256 + threadIdx.x;
        out[B_ * C_ + idx] = pool[idx];
    } else {
        int t = threadIdx.x;
        if (t < B_ * C_) {
            int b = t / C_, c = t % C_;
            const float* hp = h + b * D_;
            const float* wp = w2 + c * D_;
            float s = b2[c];
            for (int d = 0; d < D_; d++) s = fmaf(hp[d], wp[d], s);
            out[b * C_ + c] = s;
        }
    }
}

// ---------------- orchestration ----------------
extern "C" void kernel_launch(void* const* d_in, const int* in_sizes, int n_in,
                              void* d_out, int out_size)
{
    const float* x     = (const float*)d_in[0];
    const float* fmask = (const float*)d_in[1];
    const int*   amask = (const int*)  d_in[2];
    const float* wq    = (const float*)d_in[3];
    const float* wk    = (const float*)d_in[4];
    const float* gw    = (const float*)d_in[5];
    const float* gb    = (const float*)d_in[6];
    const float* w1    = (const float*)d_in[7];
    const float* b1    = (const float*)d_in[8];
    const float* w2    = (const float*)d_in[9];
    const float* b2    = (const float*)d_in[10];
    float* out = (float*)d_out;

    float *pqk, *pwqk, *pscores, *padj, *pden, *pax, *pt1, *ppool, *phid;
    unsigned* ppoolu;
    cudaGetSymbolAddress((void**)&pqk,    g_qk);
    cudaGetSymbolAddress((void**)&pwqk,   g_wqk);
    cudaGetSymbolAddress((void**)&pscores,g_scores);
    cudaGetSymbolAddress((void**)&padj,   g_adj);
    cudaGetSymbolAddress((void**)&pden,   g_den);
    cudaGetSymbolAddress((void**)&pax,    g_ax);
    cudaGetSymbolAddress((void**)&pt1,    g_t1);
    cudaGetSymbolAddress((void**)&ppoolu, g_poolu);
    cudaGetSymbolAddress((void**)&ppool,  g_pool);
    cudaGetSymbolAddress((void**)&phid,   g_hid);

    cudaFuncSetAttribute(gemm_mma<false,false,false,false,false>,
                         cudaFuncAttributeMaxDynamicSharedMemorySize, MMA_SMEM);
    cudaFuncSetAttribute(gemm_mma<true,false,false,false,false>,
                         cudaFuncAttributeMaxDynamicSharedMemorySize, MMA_SMEM);
    cudaFuncSetAttribute(gemm_mma<true,true,true,true,false>,
                         cudaFuncAttributeMaxDynamicSharedMemorySize, MMA_SMEM);
    cudaFuncSetAttribute(gemm_mma<true,true,true,true,true>,
                         cudaFuncAttributeMaxDynamicSharedMemorySize, MMA_SMEM);

    // 0) concat/transpose weights -> [768][1536] (K,N); also init pool keys
    wqk_transpose<<<(H_*D_*DK_ + 255) / 256, 256>>>(wq, wk, pwqk, ppoolu);

    // 1) fused Q|K projection: [16384 x 768] @ [768 x 1536]
    gemm_mma<false,false,false,false,false><<<dim3(QKW/128, (B_*S_)/128, 1), 128, MMA_SMEM>>>(
        x, pwqk, pqk, B_*S_, QKW, D_, D_, QKW,
        0L, 0L, 0L, 0L, 0L, 1, nullptr, nullptr, 0, nullptr, nullptr);

    // 2a) scores[b,h] = Q_bh @ K_bh^T  (batched over z = b*8+h, K=96)
    gemm_mma<true,false,false,false,false><<<dim3(4, 4, B_*H_), 128, MMA_SMEM>>>(
        pqk, pqk + D_, pscores, S_, S_, DK_, QKW, QKW,
        (long)S_*QKW, (long)DK_, (long)S_*QKW, (long)DK_, (long)S_*S_, H_,
        nullptr, nullptr, 0, nullptr, nullptr);

    // 2b) streaming softmax + head-mean -> adj, denom
    softmax_mean_kernel<<<dim3(16, B_), 512>>>(pscores, fmask, padj, pden);

    // 3) GCN layers
    {
        dim3 g(D_/128, S_/128, B_);   // (6, 4, 32)
        gemm_mma<false,false,false,false,false><<<g, 128, MMA_SMEM>>>(
            padj, x, pax, S_, D_, S_, S_, D_,
            (long)S_*S_, 0L, (long)S_*D_, 0L, (long)S_*D_, 1,
            nullptr, nullptr, 0, nullptr, nullptr);
        gemm_mma<true,true,true,true,false><<<g, 128, MMA_SMEM>>>(
            pax, gw, pt1, S_, D_, D_, D_, D_,
            (long)S_*D_, 0L, 0L, 0L, (long)S_*D_, 1,
            gb, pden, S_, nullptr, nullptr);
        gemm_mma<false,false,false,false,false><<<g, 128, MMA_SMEM>>>(
            padj, pt1, pax, S_, D_, S_, S_, D_,
            (long)S_*S_, 0L, (long)S_*D_, 0L, (long)S_*D_, 1,
            nullptr, nullptr, 0, nullptr, nullptr);
        // t2 GEMM with fused aspect max-pool (no t2 materialization)
        gemm_mma<true,true,true,true,true><<<g, 128, MMA_SMEM>>>(
            pax, gw + (long)D_*D_, pt1, S_, D_, D_, D_, D_,
            (long)S_*D_, 0L, 0L, 0L, (long)S_*D_, 1,
            gb + D_, pden, S_, amask, ppoolu);
    }

    // 4) decode pooled keys -> preds
    pool_decode<<<(B_*D_ + 255) / 256, 256>>>(ppoolu, ppool);

    // 5) FFN1
    sgemm_small<true,true,true><<<dim3(12, 1, 1), 256>>>(
        ppool, w1, phid, B_, D_, D_, b1);

    // 6) FFN2 + output
    ffn2_kernel<<<97, 256>>>(phid, w2, b2, ppool, out);
}

// round 17
// speedup vs baseline: 1.2696x; 1.0084x over previous
#include <cuda_runtime.h>
#include <cuda_fp16.h>
#include <math.h>
#include <stdint.h>

#define B_  32
#define S_  512
#define D_  768
#define H_  8
#define DK_ 96
#define C_  3
#define QKW 1536   // fused q|k width

// ---------------- scratch (device globals; no allocs allowed) ----------------
__device__ float    g_qk    [(long)B_*S_*QKW];
__device__ float    g_wqk   [D_*QKW];
__device__ __half   g_scores[(long)B_*H_*S_*S_];   // 128 MiB (fp16)
__device__ float    g_adj   [(long)B_*S_*S_];
__device__ float    g_den   [B_*S_];
__device__ float    g_ax    [B_*S_*D_];
__device__ float    g_t1    [B_*S_*D_];
__device__ unsigned g_poolu [B_*D_];
__device__ float    g_pool  [B_*D_];
__device__ float    g_hid   [B_*D_];

// ---------------- bf16x3 helpers ----------------
__device__ __forceinline__ void bsplit2(float x, float y, uint32_t& h, uint32_t& l) {
    uint32_t bx = __float_as_uint(x), by = __float_as_uint(y);
    h = __byte_perm(bx, by, 0x7632);          // {y_hi16, x_hi16}
    float lx = x - __uint_as_float(bx & 0xFFFF0000u);
    float ly = y - __uint_as_float(by & 0xFFFF0000u);
    asm("cvt.rn.bf16x2.f32 %0, %1, %2;" : "=r"(l) : "f"(ly), "f"(lx));
}
__device__ __forceinline__ void mma_bf16(float* c, const uint32_t* a, const uint32_t* b) {
    asm volatile(
        "mma.sync.aligned.m16n8k16.row.col.f32.bf16.bf16.f32 "
        "{%0,%1,%2,%3}, {%4,%5,%6,%7}, {%8,%9}, {%0,%1,%2,%3};"
        : "+f"(c[0]), "+f"(c[1]), "+f"(c[2]), "+f"(c[3])
        : "r"(a[0]), "r"(a[1]), "r"(a[2]), "r"(a[3]), "r"(b[0]), "r"(b[1]));
}
__device__ __forceinline__ void ldsm4(uint32_t& r0, uint32_t& r1,
                                      uint32_t& r2, uint32_t& r3, uint32_t addr) {
    asm volatile("ldmatrix.sync.aligned.m8n8.x4.shared.b16 {%0,%1,%2,%3}, [%4];"
                 : "=r"(r0), "=r"(r1), "=r"(r2), "=r"(r3) : "r"(addr));
}
__device__ __forceinline__ uint32_t smem_addr32(const void* p) {
    uint32_t a;
    asm("{ .reg .u64 t; cvta.to.shared.u64 t, %1; cvt.u32.u64 %0, t; }"
        : "=r"(a) : "l"(p));
    return a;
}
// order-preserving float->uint key (monotonic)
__device__ __forceinline__ unsigned fkey(float f) {
    int i = __float_as_int(f);
    return (i >= 0) ? ((unsigned)i | 0x80000000u) : ~(unsigned)i;
}
__device__ __forceinline__ float funkey(unsigned u) {
    int i = (u & 0x80000000u) ? (int)(u & 0x7FFFFFFFu) : (int)(~u);
    return __int_as_float(i);
}

// ---------------- fast exp ----------------
__device__ __forceinline__ float fast_exp(float x) {
    float y = fmaxf(x * 1.4426950408889634f, -126.0f);
    float t = __fadd_rn(y, 12582912.0f);
    float n = __fsub_rn(t, 12582912.0f);
    float f = __fsub_rn(y, n);
    float p = 0.0013333558f;
    p = fmaf(p, f, 0.0096181291f);
    p = fmaf(p, f, 0.0555041087f);
    p = fmaf(p, f, 0.2402265070f);
    p = fmaf(p, f, 0.6931471806f);
    p = fmaf(p, f, 1.0f);
    int e = (int)n;
    return __int_as_float(__float_as_int(p) + (e << 23));
}

// ---------------- weight concat/transpose: [H,D,DK]x2 -> [D, q|k] (K,N) -----
__global__ void wqk_transpose(const float* __restrict__ wq,
                              const float* __restrict__ wk,
                              float* __restrict__ out,
                              unsigned* __restrict__ poolu)
{
    int idx = blockIdx.x * 256 + threadIdx.x;
    if (idx < B_ * D_) poolu[idx] = 0x39E3BFFFu;   // fkey(-10000.0f)
    if (idx >= H_ * D_ * DK_) return;
    int h = idx / (D_ * DK_);
    int r = idx % (D_ * DK_);
    int d = r / DK_, j = r % DK_;
    out[(long)d * QKW + h * DK_ + j]       = wq[idx];
    out[(long)d * QKW + D_ + h * DK_ + j]  = wk[idx];
}

// ========= bf16x3 GEMM: 128x128 tile, 4 warps of 64x64, KC=16, ldmatrix =====
// TRANSB: B is [N,K] rows; else [K,N]. Two-level batch z = zb*hdiv + zh.
// POOL: skip C store; aspect-masked column-max into poolu via atomicMax.
// HOUT: store C as fp16 (scores).
#define SRW 12
#define TSZ (128 * SRW)
#define MMA_SMEM (8 * TSZ * 4)          // 49152 B

template<bool TRANSB, bool BIAS, bool RELU, bool DENOM, bool POOL, bool HOUT>
__global__ __launch_bounds__(128, 2) void gemm_mma(
    const float* __restrict__ A, const float* __restrict__ Bm, float* __restrict__ C,
    int M, int N, int K, int lda, int ldb,
    long sA, long hA, long sB, long hB, long sC, int hdiv,
    const float* __restrict__ bias, const float* __restrict__ denom, int dstride,
    const int* __restrict__ am, unsigned* __restrict__ poolu)
{
    extern __shared__ uint32_t sm[];

    const int tid  = threadIdx.x;
    const int wid  = tid >> 5;
    const int lane = tid & 31;
    const int t    = lane & 3;
    const int g    = lane >> 2;
    const int wr   = wid & 1;
    const int wc   = wid >> 1;

    const int z  = blockIdx.z;
    const int zb = z / hdiv;
    const int zh = z - zb * hdiv;
    A  += (long)zb * sA + (long)zh * hA;
    Bm += (long)zb * sB + (long)zh * hB;
    float*  Cf = C + (long)z * sC;
    __half* Ch = (__half*)C + (long)z * sC;

    const int m0 = blockIdx.y * 128;
    const int n0 = blockIdx.x * 128;

    // ldmatrix lane offsets (bytes, within a tile buffer)
    const int r8l = lane & 7;
    const uint32_t aoffA = (uint32_t)(((wr * 64 + ((lane >> 3) & 1) * 8 + r8l) * SRW
                                       + (lane >> 4) * 4) * 4);
    const uint32_t aoffB = (uint32_t)(((wc * 64 + (lane >> 4) * 8 + r8l) * SRW
                                       + ((lane >> 3) & 1) * 4) * 4);
    const uint32_t smaddr = smem_addr32(sm);

    float acc[4][8][4];
#pragma unroll
    for (int i = 0; i < 4; i++)
#pragma unroll
        for (int j = 0; j < 8; j++)
#pragma unroll
            for (int e = 0; e < 4; e++) acc[i][j][e] = 0.0f;

    float4 pa[4], pb[4];

    auto ldgf = [&](int c) {
        const float* ap = A + (long)(m0 + tid) * lda + c * 16;
#pragma unroll
        for (int i = 0; i < 4; i++) pa[i] = *(const float4*)(ap + i * 4);
        if (TRANSB) {
            const float* bp = Bm + (long)(n0 + tid) * ldb + c * 16;
#pragma unroll
            for (int i = 0; i < 4; i++) pb[i] = *(const float4*)(bp + i * 4);
        } else {
            const float* bp = Bm + (long)(c * 16) * ldb + n0 + tid;
#pragma unroll
            for (int i = 0; i < 4; i++) {
                pb[i].x = bp[(long)(4 * i + 0) * ldb];
                pb[i].y = bp[(long)(4 * i + 1) * ldb];
                pb[i].z = bp[(long)(4 * i + 2) * ldb];
                pb[i].w = bp[(long)(4 * i + 3) * ldb];
            }
        }
    };
    auto stsf = [&](int s) {
        uint32_t hw[8], lw[8];
#pragma unroll
        for (int i = 0; i < 4; i++) {
            bsplit2(pa[i].x, pa[i].y, hw[2*i],   lw[2*i]);
            bsplit2(pa[i].z, pa[i].w, hw[2*i+1], lw[2*i+1]);
        }
        uint32_t* dah = sm + s * TSZ + tid * SRW;
        uint32_t* dal = sm + (2 + s) * TSZ + tid * SRW;
        *(uint4*)(dah)     = make_uint4(hw[0], hw[1], hw[2], hw[3]);
        *(uint4*)(dah + 4) = make_uint4(hw[4], hw[5], hw[6], hw[7]);
        *(uint4*)(dal)     = make_uint4(lw[0], lw[1], lw[2], lw[3]);
        *(uint4*)(dal + 4) = make_uint4(lw[4], lw[5], lw[6], lw[7]);
#pragma unroll
        for (int i = 0; i < 4; i++) {
            bsplit2(pb[i].x, pb[i].y, hw[2*i],   lw[2*i]);
            bsplit2(pb[i].z, pb[i].w, hw[2*i+1], lw[2*i+1]);
        }
        uint32_t* dbh = sm + (4 + s) * TSZ + tid * SRW;
        uint32_t* dbl = sm + (6 + s) * TSZ + tid * SRW;
        *(uint4*)(dbh)     = make_uint4(hw[0], hw[1], hw[2], hw[3]);
        *(uint4*)(dbh + 4) = make_uint4(hw[4], hw[5], hw[6], hw[7]);
        *(uint4*)(dbl)     = make_uint4(lw[0], lw[1], lw[2], lw[3]);
        *(uint4*)(dbl + 4) = make_uint4(lw[4], lw[5], lw[6], lw[7]);
    };

    auto compute = [&](int s) {
        const uint32_t aHb = smaddr + (uint32_t)((s)     * TSZ * 4) + aoffA;
        const uint32_t aLb = smaddr + (uint32_t)((2 + s) * TSZ * 4) + aoffA;
        const uint32_t bHb = smaddr + (uint32_t)((4 + s) * TSZ * 4) + aoffB;
        const uint32_t bLb = smaddr + (uint32_t)((6 + s) * TSZ * 4) + aoffB;
        uint32_t ah[4][4], al[4][4];
#pragma unroll
        for (int mt = 0; mt < 4; mt++) {
            const uint32_t o = mt * (16 * SRW * 4);
            ldsm4(ah[mt][0], ah[mt][1], ah[mt][2], ah[mt][3], aHb + o);
            ldsm4(al[mt][0], al[mt][1], al[mt][2], al[mt][3], aLb + o);
        }
#pragma unroll
        for (int p = 0; p < 4; p++) {
            const uint32_t o = p * (16 * SRW * 4);
            uint32_t bh[4], bl[4];
            ldsm4(bh[0], bh[1], bh[2], bh[3], bHb + o);
            ldsm4(bl[0], bl[1], bl[2], bl[3], bLb + o);
#pragma unroll
            for (int mt = 0; mt < 4; mt++) {
                mma_bf16(acc[mt][2*p],     ah[mt], bh);
                mma_bf16(acc[mt][2*p],     ah[mt], bl);
                mma_bf16(acc[mt][2*p],     al[mt], bh);
                mma_bf16(acc[mt][2*p + 1], ah[mt], bh + 2);
                mma_bf16(acc[mt][2*p + 1], ah[mt], bl + 2);
                mma_bf16(acc[mt][2*p + 1], al[mt], bh + 2);
            }
        }
    };

    const int NC = K >> 4;
    ldgf(0); stsf(0);
    __syncthreads();
    for (int it = 1; it < NC; it++) {
        ldgf(it);
        compute((it - 1) & 1);
        stsf(it & 1);
        __syncthreads();
    }
    compute((NC - 1) & 1);

    // ---- epilogue ----
    float cmax[8][2];
    if (POOL) {
#pragma unroll
        for (int nt = 0; nt < 8; nt++) { cmax[nt][0] = -1e30f; cmax[nt][1] = -1e30f; }
    }
#pragma unroll
    for (int mt = 0; mt < 4; mt++) {
        const int row0 = m0 + wr * 64 + mt * 16 + g;
        const int row1 = row0 + 8;
        float inv0 = 1.0f, inv1 = 1.0f;
        if (DENOM) {
            inv0 = 1.0f / denom[(long)zb * dstride + row0];
            inv1 = 1.0f / denom[(long)zb * dstride + row1];
        }
        float mk0 = 0.0f, mk1 = 0.0f;
        if (POOL) {
            mk0 = (am[(long)zb * S_ + row0] == 1) ? 1.0f : 0.0f;
            mk1 = (am[(long)zb * S_ + row1] == 1) ? 1.0f : 0.0f;
        }
#pragma unroll
        for (int nt = 0; nt < 8; nt++) {
            const int col = n0 + wc * 64 + nt * 8 + 2 * t;
            float bv0 = 0.0f, bv1 = 0.0f;
            if (BIAS) { bv0 = bias[col]; bv1 = bias[col + 1]; }
            float v0 = acc[mt][nt][0] + bv0;
            float v1 = acc[mt][nt][1] + bv1;
            float v2 = acc[mt][nt][2] + bv0;
            float v3 = acc[mt][nt][3] + bv1;
            if (DENOM) { v0 *= inv0; v1 *= inv0; v2 *= inv1; v3 *= inv1; }
            if (RELU) {
                v0 = fmaxf(v0, 0.0f); v1 = fmaxf(v1, 0.0f);
                v2 = fmaxf(v2, 0.0f); v3 = fmaxf(v3, 0.0f);
            }
            if (POOL) {
                cmax[nt][0] = fmaxf(cmax[nt][0], mk0 ? v0 : -1e30f);
                cmax[nt][0] = fmaxf(cmax[nt][0], mk1 ? v2 : -1e30f);
                cmax[nt][1] = fmaxf(cmax[nt][1], mk0 ? v1 : -1e30f);
                cmax[nt][1] = fmaxf(cmax[nt][1], mk1 ? v3 : -1e30f);
            } else if (HOUT) {
                *(__half2*)&Ch[(long)row0 * N + col] = __floats2half2_rn(v0, v1);
                *(__half2*)&Ch[(long)row1 * N + col] = __floats2half2_rn(v2, v3);
            } else {
                *(float2*)&Cf[(long)row0 * N + col] = make_float2(v0, v1);
                *(float2*)&Cf[(long)row1 * N + col] = make_float2(v2, v3);
            }
        }
    }
    if (POOL) {
        __syncthreads();
        float* part = (float*)sm;
        const int slot = wr * 8 + g;
#pragma unroll
        for (int nt = 0; nt < 8; nt++) {
            const int c0 = wc * 64 + nt * 8 + 2 * t;
            part[(c0    ) * 17 + slot] = cmax[nt][0];
            part[(c0 + 1) * 17 + slot] = cmax[nt][1];
        }
        __syncthreads();
        if (tid < 128) {
            float m = -1e30f;
#pragma unroll
            for (int j = 0; j < 16; j++) m = fmaxf(m, part[tid * 17 + j]);
            atomicMax(&poolu[(long)zb * D_ + n0 + tid], fkey(m));
        }
    }
}

// ---------------- pool decode: uint keys -> float ----------------
__global__ void pool_decode(const unsigned* __restrict__ pu, float* __restrict__ pf)
{
    int i = blockIdx.x * 256 + threadIdx.x;
    if (i < B_ * D_) pf[i] = funkey(pu[i]);
}

// ======= streaming softmax + head-mean: scores(fp16) -> adj, denom ==========
__global__ __launch_bounds__(512, 1) void softmax_mean_kernel(
    const __half* __restrict__ scores, const float* __restrict__ fmask,
    float* __restrict__ adj, float* __restrict__ denom)
{
    const int b   = blockIdx.y;
    const int r0  = blockIdx.x * 32;
    const int wid = threadIdx.x >> 5;
    const int lane = threadIdx.x & 31;
    const float rs = 0.10206207261596577f;   // 1/sqrt(96)

    float fmv[16];
#pragma unroll
    for (int c = 0; c < 4; c++) {
        float4 v = *(const float4*)&fmask[b * S_ + c * 128 + lane * 4];
        fmv[c*4+0] = v.x; fmv[c*4+1] = v.y; fmv[c*4+2] = v.z; fmv[c*4+3] = v.w;
    }

#pragma unroll
    for (int rr = 0; rr < 2; rr++) {
        const int i  = r0 + wid * 2 + rr;
        const float fr = fmask[b * S_ + i];
        float acc[16];
#pragma unroll
        for (int e = 0; e < 16; e++) acc[e] = 0.0f;

        for (int h = 0; h < H_; h++) {
            const __half* p = scores + ((long)(b * H_ + h) * S_ + i) * S_;
            float ev[16];
#pragma unroll
            for (int c = 0; c < 4; c++) {
                uint2 raw = *(const uint2*)&p[c * 128 + lane * 4];
                float2 f0 = __half22float2(*(__half2*)&raw.x);
                float2 f1 = __half22float2(*(__half2*)&raw.y);
                ev[c*4+0] = f0.x; ev[c*4+1] = f0.y;
                ev[c*4+2] = f1.x; ev[c*4+3] = f1.y;
            }
            float mx = -INFINITY;
#pragma unroll
            for (int e = 0; e < 16; e++) {
                float vv = (fr * fmv[e] == 0.0f) ? -1e9f : ev[e] * rs;
                ev[e] = vv;
                mx = fmaxf(mx, vv);
            }
            mx = fmaxf(mx, __shfl_xor_sync(0xffffffffu, mx, 1));
            mx = fmaxf(mx, __shfl_xor_sync(0xffffffffu, mx, 2));
            mx = fmaxf(mx, __shfl_xor_sync(0xffffffffu, mx, 4));
            mx = fmaxf(mx, __shfl_xor_sync(0xffffffffu, mx, 8));
            mx = fmaxf(mx, __shfl_xor_sync(0xffffffffu, mx, 16));
            float s = 0.0f;
#pragma unroll
            for (int e = 0; e < 16; e++) {
                float x = fast_exp(ev[e] - mx);
                ev[e] = x;
                s += x;
            }
            s += __shfl_xor_sync(0xffffffffu, s, 1);
            s += __shfl_xor_sync(0xffffffffu, s, 2);
            s += __shfl_xor_sync(0xffffffffu, s, 4);
            s += __shfl_xor_sync(0xffffffffu, s, 8);
            s += __shfl_xor_sync(0xffffffffu, s, 16);
            const float inv = 1.0f / (8.0f * s);
#pragma unroll
            for (int e = 0; e < 16; e++) acc[e] = fmaf(ev[e], inv, acc[e]);
        }

        float* arow = adj + ((long)b * S_ + i) * S_;
#pragma unroll
        for (int c = 0; c < 4; c++) {
            float4 o;
#pragma unroll
            for (int e = 0; e < 4; e++) {
                int j = c * 128 + lane * 4 + e;
                float v = acc[c * 4 + e];
                if (j == i) { denom[b * S_ + i] = 3.0f - v; v = 1.0f; }
                ((float*)&o)[e] = v;
            }
            *(float4*)&arow[c * 128 + lane * 4] = o;
        }
    }
}

// ---------------- small guarded SGEMM (FFN1 only: M=32) ----------------------
template<bool TRANSB, bool BIAS, bool RELU>
__global__ __launch_bounds__(256) void sgemm_small(
    const float* __restrict__ A, const float* __restrict__ Bm, float* __restrict__ C,
    int M, int N, int K, const float* __restrict__ bias)
{
    __shared__ float As[16][68];
    __shared__ float Bs[16][68];
    const int m0 = blockIdx.y * 64, n0 = blockIdx.x * 64;
    const int tid = threadIdx.x;
    const int tx = tid & 15, ty = tid >> 4;
    float acc[4][4];
#pragma unroll
    for (int i = 0; i < 4; i++)
#pragma unroll
        for (int j = 0; j < 4; j++) acc[i][j] = 0.0f;
    const int arow = tid >> 2, akq = (tid & 3) * 4;
    for (int k0 = 0; k0 < K; k0 += 16) {
        float4 av = make_float4(0.f,0.f,0.f,0.f);
        if (m0 + arow < M)
            av = *(const float4*)&A[(long)(m0 + arow) * K + k0 + akq];
        As[akq+0][arow]=av.x; As[akq+1][arow]=av.y;
        As[akq+2][arow]=av.z; As[akq+3][arow]=av.w;
        if (!TRANSB) {
            const int kr = tid >> 4, nq = (tid & 15) * 4;
            float4 bv = make_float4(0.f,0.f,0.f,0.f);
            if (n0 + nq < N)
                bv = *(const float4*)&Bm[(long)(k0+kr)*N + n0 + nq];
            Bs[kr][nq+0]=bv.x; Bs[kr][nq+1]=bv.y; Bs[kr][nq+2]=bv.z; Bs[kr][nq+3]=bv.w;
        } else {
            const int nrow = tid >> 2, kq = (tid & 3) * 4;
            float4 bv = make_float4(0.f,0.f,0.f,0.f);
            if (n0 + nrow < N)
                bv = *(const float4*)&Bm[(long)(n0+nrow)*K + k0 + kq];
            Bs[kq+0][nrow]=bv.x; Bs[kq+1][nrow]=bv.y; Bs[kq+2][nrow]=bv.z; Bs[kq+3][nrow]=bv.w;
        }
        __syncthreads();
#pragma unroll
        for (int kk = 0; kk < 16; kk++) {
            float4 a = *(const float4*)&As[kk][ty*4];
            float4 b = *(const float4*)&Bs[kk][tx*4];
            acc[0][0]=fmaf(a.x,b.x,acc[0][0]); acc[0][1]=fmaf(a.x,b.y,acc[0][1]);
            acc[0][2]=fmaf(a.x,b.z,acc[0][2]); acc[0][3]=fmaf(a.x,b.w,acc[0][3]);
            acc[1][0]=fmaf(a.y,b.x,acc[1][0]); acc[1][1]=fmaf(a.y,b.y,acc[1][1]);
            acc[1][2]=fmaf(a.y,b.z,acc[1][2]); acc[1][3]=fmaf(a.y,b.w,acc[1][3]);
            acc[2][0]=fmaf(a.z,b.x,acc[2][0]); acc[2][1]=fmaf(a.z,b.y,acc[2][1]);
            acc[2][2]=fmaf(a.z,b.z,acc[2][2]); acc[2][3]=fmaf(a.z,b.w,acc[2][3]);
            acc[3][0]=fmaf(a.w,b.x,acc[3][0]); acc[3][1]=fmaf(a.w,b.y,acc[3][1]);
            acc[3][2]=fmaf(a.w,b.z,acc[3][2]); acc[3][3]=fmaf(a.w,b.w,acc[3][3]);
        }
        __syncthreads();
    }
#pragma unroll
    for (int i = 0; i < 4; i++) {
        int m = m0 + ty*4 + i;
        if (m >= M) continue;
#pragma unroll
        for (int j = 0; j < 4; j++) {
            int n = n0 + tx*4 + j;
            if (n < N) {
                float v = acc[i][j];
                if (BIAS) v += bias[n];
                if (RELU) v = fmaxf(v, 0.0f);
                C[(long)m * N + n] = v;
            }
        }
    }
}

// ---------------- FFN2 + output assembly ----------------
__global__ void ffn2_kernel(const float* __restrict__ h,
                            const float* __restrict__ w2,
                            const float* __restrict__ b2,
                            const float* __restrict__ pool,
                            float* __restrict__ out)
{
    int bid = blockIdx.x;
    if (bid < 96) {
        int idx = bid * 256 + threadIdx.x;
        out[B_ * C_ + idx] = pool[idx];
    } else {
        int t = threadIdx.x;
        if (t < B_ * C_) {
            int b = t / C_, c = t % C_;
            const float* hp = h + b * D_;
            const float* wp = w2 + c * D_;
            float s = b2[c];
            for (int d = 0; d < D_; d++) s = fmaf(hp[d], wp[d], s);
            out[b * C_ + c] = s;
        }
    }
}

// ---------------- orchestration ----------------
extern "C" void kernel_launch(void* const* d_in, const int* in_sizes, int n_in,
                              void* d_out, int out_size)
{
    const float* x     = (const float*)d_in[0];
    const float* fmask = (const float*)d_in[1];
    const int*   amask = (const int*)  d_in[2];
    const float* wq    = (const float*)d_in[3];
    const float* wk    = (const float*)d_in[4];
    const float* gw    = (const float*)d_in[5];
    const float* gb    = (const float*)d_in[6];
    const float* w1    = (const float*)d_in[7];
    const float* b1    = (const float*)d_in[8];
    const float* w2    = (const float*)d_in[9];
    const float* b2    = (const float*)d_in[10];
    float* out = (float*)d_out;

    float *pqk, *pwqk, *padj, *pden, *pax, *pt1, *ppool, *phid;
    __half* pscores;
    unsigned* ppoolu;
    cudaGetSymbolAddress((void**)&pqk,    g_qk);
    cudaGetSymbolAddress((void**)&pwqk,   g_wqk);
    cudaGetSymbolAddress((void**)&pscores,g_scores);
    cudaGetSymbolAddress((void**)&padj,   g_adj);
    cudaGetSymbolAddress((void**)&pden,   g_den);
    cudaGetSymbolAddress((void**)&pax,    g_ax);
    cudaGetSymbolAddress((void**)&pt1,    g_t1);
    cudaGetSymbolAddress((void**)&ppoolu, g_poolu);
    cudaGetSymbolAddress((void**)&ppool,  g_pool);
    cudaGetSymbolAddress((void**)&phid,   g_hid);

    cudaFuncSetAttribute(gemm_mma<false,false,false,false,false,false>,
                         cudaFuncAttributeMaxDynamicSharedMemorySize, MMA_SMEM);
    cudaFuncSetAttribute(gemm_mma<true,false,false,false,false,true>,
                         cudaFuncAttributeMaxDynamicSharedMemorySize, MMA_SMEM);
    cudaFuncSetAttribute(gemm_mma<true,true,true,true,false,false>,
                         cudaFuncAttributeMaxDynamicSharedMemorySize, MMA_SMEM);
    cudaFuncSetAttribute(gemm_mma<true,true,true,true,true,false>,
                         cudaFuncAttributeMaxDynamicSharedMemorySize, MMA_SMEM);

    // 0) concat/transpose weights -> [768][1536] (K,N); also init pool keys
    wqk_transpose<<<(H_*D_*DK_ + 255) / 256, 256>>>(wq, wk, pwqk, ppoolu);

    // 1) fused Q|K projection: [16384 x 768] @ [768 x 1536]
    gemm_mma<false,false,false,false,false,false><<<dim3(QKW/128, (B_*S_)/128, 1), 128, MMA_SMEM>>>(
        x, pwqk, pqk, B_*S_, QKW, D_, D_, QKW,
        0L, 0L, 0L, 0L, 0L, 1, nullptr, nullptr, 0, nullptr, nullptr);

    // 2a) scores[b,h] = Q_bh @ K_bh^T  (fp16 out; batched, K=96)
    gemm_mma<true,false,false,false,false,true><<<dim3(4, 4, B_*H_), 128, MMA_SMEM>>>(
        pqk, pqk + D_, (float*)pscores, S_, S_, DK_, QKW, QKW,
        (long)S_*QKW, (long)DK_, (long)S_*QKW, (long)DK_, (long)S_*S_, H_,
        nullptr, nullptr, 0, nullptr, nullptr);

    // 2b) streaming softmax + head-mean -> adj, denom
    softmax_mean_kernel<<<dim3(16, B_), 512>>>(pscores, fmask, padj, pden);

    // 3) GCN layers
    {
        dim3 g(D_/128, S_/128, B_);   // (6, 4, 32)
        gemm_mma<false,false,false,false,false,false><<<g, 128, MMA_SMEM>>>(
            padj, x, pax, S_, D_, S_, S_, D_,
            (long)S_*S_, 0L, (long)S_*D_, 0L, (long)S_*D_, 1,
            nullptr, nullptr, 0, nullptr, nullptr);
        gemm_mma<true,true,true,true,false,false><<<g, 128, MMA_SMEM>>>(
            pax, gw, pt1, S_, D_, D_, D_, D_,
            (long)S_*D_, 0L, 0L, 0L, (long)S_*D_, 1,
            gb, pden, S_, nullptr, nullptr);
        gemm_mma<false,false,false,false,false,false><<<g, 128, MMA_SMEM>>>(
            padj, pt1, pax, S_, D_, S_, S_, D_,
            (long)S_*S_, 0L, (long)S_*D_, 0L, (long)S_*D_, 1,
            nullptr, nullptr, 0, nullptr, nullptr);
        // t2 GEMM with fused aspect max-pool (no t2 materialization)
        gemm_mma<true,true,true,true,true,false><<<g, 128, MMA_SMEM>>>(
            pax, gw + (long)D_*D_, pt1, S_, D_, D_, D_, D_,
            (long)S_*D_, 0L, 0L, 0L, (long)S_*D_, 1,
            gb + D_, pden, S_, amask, ppoolu);
    }

    // 4) decode pooled keys -> preds
    pool_decode<<<(B_*D_ + 255) / 256, 256>>>(ppoolu, ppool);

    // 5) FFN1
    sgemm_small<true,true,true><<<dim3(12, 1, 1), 256>>>(
        ppool, w1, phid, B_, D_, D_, b1);

    // 6) FFN2 + output
    ffn2_kernel<<<97, 256>>>(phid, w2, b2, ppool, out);
}